// round 3
// baseline (speedup 1.0000x reference)
#include <cuda_runtime.h>

#define D 128
#define MAXN 100000
#define MAXE 1600000

typedef unsigned long long ull;

// ---------------- device scratch (no allocations allowed) ----------------
__device__ int   g_cnt[MAXN];
__device__ int   g_rowptr[MAXN + 1];
__device__ int   g_cursor[MAXN];
__device__ int   g_csr[MAXE];
__device__ float g_dinv[MAXN];
__device__ int   g_bsum[128];
__device__ int   g_boff[128];
__device__ float g_h[(size_t)MAXN * D];   // layer dense output
__device__ float g_x[(size_t)MAXN * D];   // layer-1 activation

// ---------------- packed f32x2 helpers (FFMA2) ----------------
__device__ __forceinline__ ull pack2(float x, float y) {
    ull r;
    asm("mov.b64 %0, {%1, %2};" : "=l"(r) : "f"(x), "f"(y));
    return r;
}
__device__ __forceinline__ void unpack2(ull v, float& x, float& y) {
    asm("mov.b64 {%0, %1}, %2;" : "=f"(x), "=f"(y) : "l"(v));
}
__device__ __forceinline__ void ffma2(ull& acc, ull a, ull b) {
    asm("fma.rn.f32x2 %0, %1, %2, %0;" : "+l"(acc) : "l"(a), "l"(b));
}

// ---------------- CSR build ----------------
__global__ void zero_cnt_k(int n) {
    int i = blockIdx.x * blockDim.x + threadIdx.x;
    if (i < n) g_cnt[i] = 0;
}

__global__ void count_k(const int* __restrict__ dst, int E) {
    int i = blockIdx.x * blockDim.x + threadIdx.x;
    if (i < E) atomicAdd(&g_cnt[dst[i]], 1);
}

// hierarchical scan, stage 1: each block scans 1024 counts (4/thread)
__global__ void scan1_k(int n) {
    __shared__ int wsum[8];
    int tid = threadIdx.x, lane = tid & 31, warp = tid >> 5;
    int base = blockIdx.x * 1024 + tid * 4;
    int4 v = make_int4(0, 0, 0, 0);
    if (base + 3 < n) {
        v = *(const int4*)(g_cnt + base);
    } else {
        if (base + 0 < n) v.x = g_cnt[base + 0];
        if (base + 1 < n) v.y = g_cnt[base + 1];
        if (base + 2 < n) v.z = g_cnt[base + 2];
    }
    int s = v.x + v.y + v.z + v.w;
    int t = s;
    #pragma unroll
    for (int o = 1; o < 32; o <<= 1) {
        int u = __shfl_up_sync(0xffffffffu, t, o);
        if (lane >= o) t += u;
    }
    if (lane == 31) wsum[warp] = t;
    __syncthreads();
    if (warp == 0 && lane < 8) {
        int w = wsum[lane];
        #pragma unroll
        for (int o = 1; o < 8; o <<= 1) {
            int u = __shfl_up_sync(0xffu, w, o);
            if (lane >= o) w += u;
        }
        wsum[lane] = w;
    }
    __syncthreads();
    int excl = t - s + (warp ? wsum[warp - 1] : 0);
    int p0 = excl, p1 = p0 + v.x, p2 = p1 + v.y, p3 = p2 + v.z;
    if (base + 3 < n) {
        *(int4*)(g_rowptr + base) = make_int4(p0, p1, p2, p3);
    } else {
        if (base + 0 < n) g_rowptr[base + 0] = p0;
        if (base + 1 < n) g_rowptr[base + 1] = p1;
        if (base + 2 < n) g_rowptr[base + 2] = p2;
    }
    if (tid == 255) g_bsum[blockIdx.x] = excl + s;
}

// stage 2: scan up to 128 block sums (single small block)
__global__ void scan2_k(int n, int nb) {
    __shared__ int wsum[4];
    int tid = threadIdx.x, lane = tid & 31, warp = tid >> 5;   // 128 threads
    int v = (tid < nb) ? g_bsum[tid] : 0;
    int t = v;
    #pragma unroll
    for (int o = 1; o < 32; o <<= 1) {
        int u = __shfl_up_sync(0xffffffffu, t, o);
        if (lane >= o) t += u;
    }
    if (lane == 31) wsum[warp] = t;
    __syncthreads();
    if (warp == 0 && lane < 4) {
        int w = wsum[lane];
        #pragma unroll
        for (int o = 1; o < 4; o <<= 1) {
            int u = __shfl_up_sync(0xfu, w, o);
            if (lane >= o) w += u;
        }
        wsum[lane] = w;
    }
    __syncthreads();
    int excl = t - v + (warp ? wsum[warp - 1] : 0);
    if (tid < nb) g_boff[tid] = excl;
    if (tid == 127) g_rowptr[n] = wsum[3];
}

// stage 3: add block offsets; fused dinv + cursor init
__global__ void scan3_k(int n) {
    int i = blockIdx.x * blockDim.x + threadIdx.x;
    if (i < n) {
        int rp = g_rowptr[i] + g_boff[i >> 10];
        g_rowptr[i] = rp;
        g_cursor[i] = rp;
        g_dinv[i] = rsqrtf((float)(g_cnt[i] + 1));   // +1 self-loop
    }
}

__global__ void fill_k(const int* __restrict__ src, const int* __restrict__ dst, int E) {
    int i = blockIdx.x * blockDim.x + threadIdx.x;
    if (i < E) {
        int p = atomicAdd(&g_cursor[dst[i]], 1);
        g_csr[p] = src[i];
    }
}

// ---------------- dense transform: g_h = X @ W ----------------
// 256 threads; warp handles 4 rows; lane owns col pairs (2l,2l+1) and (64+2l,64+2l+1).
// W staged as packed b64 col-pairs (direct LDS.64); X staged pre-splatted (x,x).
__global__ void gemm_k(const float* __restrict__ X, const float* __restrict__ W, int n) {
    extern __shared__ char smraw[];
    ull* sW = (ull*)smraw;          // [k][c2] : 128*64 ull = 64KB
    ull* sX = sW + D * 64;          // [r][k] splatted : 32*128 ull = 32KB
    int tid = threadIdx.x;

    const ull* W2 = (const ull*)W;  // row-major pairs are contiguous
    for (int i = tid; i < D * 64; i += 256) sW[i] = W2[i];

    int row0 = blockIdx.x * 32;
    for (int i = tid; i < 32 * D; i += 256) {
        int r = i >> 7, k = i & 127;
        float v = (row0 + r < n) ? X[(size_t)(row0 + r) * D + k] : 0.f;
        sX[r * D + k] = pack2(v, v);
    }
    __syncthreads();

    int warp = tid >> 5, lane = tid & 31;
    const ull* xr = sX + (warp * 4) * D;
    ull acc[4][2] = {};

    #pragma unroll 4
    for (int k = 0; k < D; k++) {
        ull wa = sW[k * 64 + lane];
        ull wb = sW[k * 64 + 32 + lane];
        #pragma unroll
        for (int r = 0; r < 4; r++) {
            ull xv = xr[r * D + k];
            ffma2(acc[r][0], xv, wa);
            ffma2(acc[r][1], xv, wb);
        }
    }

    #pragma unroll
    for (int r = 0; r < 4; r++) {
        int row = row0 + warp * 4 + r;
        if (row < n) {
            ull* hp = (ull*)(g_h + (size_t)row * D);
            hp[lane]      = acc[r][0];
            hp[32 + lane] = acc[r][1];
        }
    }
}

// ---------------- aggregation: out = relu(agg + h), warp per node ----------------
__global__ void agg_k(float4* __restrict__ out, int n) {
    int t = blockIdx.x * blockDim.x + threadIdx.x;
    int node = t >> 5;
    int lane = t & 31;
    if (node >= n) return;

    const float4* h4 = (const float4*)g_h;
    float dv = g_dinv[node];
    float4 hv = h4[(size_t)node * 32 + lane];
    float ws = dv * dv;                                  // self-loop norm
    float4 acc = make_float4(ws * hv.x, ws * hv.y, ws * hv.z, ws * hv.w);

    int s = g_rowptr[node], e = g_rowptr[node + 1];
    int i = s;
    for (; i + 3 < e; i += 4) {
        int u0 = g_csr[i], u1 = g_csr[i + 1], u2 = g_csr[i + 2], u3 = g_csr[i + 3];
        float w0 = g_dinv[u0] * dv, w1 = g_dinv[u1] * dv;
        float w2 = g_dinv[u2] * dv, w3 = g_dinv[u3] * dv;
        float4 v0 = h4[(size_t)u0 * 32 + lane];
        float4 v1 = h4[(size_t)u1 * 32 + lane];
        float4 v2 = h4[(size_t)u2 * 32 + lane];
        float4 v3 = h4[(size_t)u3 * 32 + lane];
        acc.x += w0 * v0.x + w1 * v1.x + w2 * v2.x + w3 * v3.x;
        acc.y += w0 * v0.y + w1 * v1.y + w2 * v2.y + w3 * v3.y;
        acc.z += w0 * v0.z + w1 * v1.z + w2 * v2.z + w3 * v3.z;
        acc.w += w0 * v0.w + w1 * v1.w + w2 * v2.w + w3 * v3.w;
    }
    for (; i < e; i++) {
        int u = g_csr[i];
        float w = g_dinv[u] * dv;
        float4 v = h4[(size_t)u * 32 + lane];
        acc.x += w * v.x; acc.y += w * v.y; acc.z += w * v.z; acc.w += w * v.w;
    }

    out[(size_t)node * 32 + lane] = make_float4(
        fmaxf(acc.x + hv.x, 0.f), fmaxf(acc.y + hv.y, 0.f),
        fmaxf(acc.z + hv.z, 0.f), fmaxf(acc.w + hv.w, 0.f));
}

// ---------------- seed gather: warp per seed ----------------
__global__ void gather_k(const int* __restrict__ seeds, const float4* __restrict__ ent,
                         float4* __restrict__ out, int ns) {
    int t = blockIdx.x * blockDim.x + threadIdx.x;
    int s = t >> 5;
    int lane = t & 31;
    if (s < ns) out[(size_t)s * 32 + lane] = ent[(size_t)seeds[s] * 32 + lane];
}

// ---------------- launch ----------------
extern "C" void kernel_launch(void* const* d_in, const int* in_sizes, int n_in,
                              void* d_out, int out_size) {
    const int*   seeds_sr = (const int*)d_in[0];
    const int*   seeds_tg = (const int*)d_in[1];
    const int*   edges_sr = (const int*)d_in[2];
    const int*   edges_tg = (const int*)d_in[3];
    const float* emb_sr   = (const float*)d_in[4];
    const float* emb_tg   = (const float*)d_in[5];
    const float* W0       = (const float*)d_in[6];
    const float* W1       = (const float*)d_in[7];

    int S = in_sizes[0];
    int E = in_sizes[2] / 2;
    int N = in_sizes[4] / D;

    float* out     = (float*)d_out;
    float* sr_seed = out;
    float* tg_seed = sr_seed + (size_t)S * D;
    float* sr_ent  = tg_seed + (size_t)S * D;
    float* tg_ent  = sr_ent  + (size_t)N * D;

    void* xaddr = nullptr;
    cudaGetSymbolAddress(&xaddr, g_x);

    int smem = (D * 64 + 32 * D) * (int)sizeof(ull);   // 96 KB
    cudaFuncSetAttribute(gemm_k, cudaFuncAttributeMaxDynamicSharedMemorySize, smem);

    int nb = (N + 1023) / 1024;

    for (int g = 0; g < 2; g++) {
        const int*   edges = g ? edges_tg : edges_sr;
        const float* emb   = g ? emb_tg   : emb_sr;
        const int*   seeds = g ? seeds_tg : seeds_sr;
        float* ent      = g ? tg_ent  : sr_ent;
        float* seed_out = g ? tg_seed : sr_seed;
        const int* src = edges;
        const int* dst = edges + E;

        // CSR build (by destination) + symmetric-norm dinv
        zero_cnt_k<<<(N + 255) / 256, 256>>>(N);
        count_k<<<(E + 255) / 256, 256>>>(dst, E);
        scan1_k<<<nb, 256>>>(N);
        scan2_k<<<1, 128>>>(N, nb);
        scan3_k<<<(N + 255) / 256, 256>>>(N);
        fill_k<<<(E + 255) / 256, 256>>>(src, dst, E);

        // layer 1: h = emb @ W0 ; x = relu(agg(h) + h)
        gemm_k<<<(N + 31) / 32, 256, smem>>>(emb, W0, N);
        agg_k<<<((size_t)N * 32 + 255) / 256, 256>>>((float4*)xaddr, N);

        // layer 2: h = x @ W1 ; ent = relu(agg(h) + h)
        gemm_k<<<(N + 31) / 32, 256, smem>>>((const float*)xaddr, W1, N);
        agg_k<<<((size_t)N * 32 + 255) / 256, 256>>>((float4*)ent, N);

        // seed gather
        gather_k<<<((size_t)S * 32 + 255) / 256, 256>>>(seeds, (const float4*)ent,
                                                        (float4*)seed_out, S);
    }
}

// round 4
// speedup vs baseline: 1.0457x; 1.0457x over previous
#include <cuda_runtime.h>
#include <cuda_bf16.h>

#define D 128
#define MAXN 100000
#define MAXE 1600000

typedef unsigned long long ull;
typedef unsigned int uint;

// ---------------- device scratch (no allocations allowed) ----------------
__device__ int   g_cnt[MAXN];
__device__ int   g_rowptr[MAXN + 1];
__device__ int   g_cursor[MAXN];
__device__ int   g_csr[MAXE];
__device__ float g_dinv[MAXN];
__device__ int   g_bsum[128];
__device__ int   g_boff[128];
__device__ float g_h[(size_t)MAXN * D];          // dense output, fp32 (self/residual)
__device__ uint  g_hb[(size_t)MAXN * (D / 2)];   // dense output, packed bf16x2 (gathers)
__device__ float g_x[(size_t)MAXN * D];          // layer-1 activation

// ---------------- packed f32x2 helpers (FFMA2) ----------------
__device__ __forceinline__ ull pack2(float x, float y) {
    ull r;
    asm("mov.b64 %0, {%1, %2};" : "=l"(r) : "f"(x), "f"(y));
    return r;
}
__device__ __forceinline__ void unpack2(ull v, float& x, float& y) {
    asm("mov.b64 {%0, %1}, %2;" : "=f"(x), "=f"(y) : "l"(v));
}
__device__ __forceinline__ void ffma2(ull& acc, ull a, ull b) {
    asm("fma.rn.f32x2 %0, %1, %2, %0;" : "+l"(acc) : "l"(a), "l"(b));
}
// exact bf16 -> fp32 decode of a packed bf16x2 word (2 ALU ops)
__device__ __forceinline__ void bf2x(uint v, float& lo, float& hi) {
    lo = __uint_as_float(v << 16);
    hi = __uint_as_float(v & 0xffff0000u);
}

// ---------------- CSR build ----------------
__global__ void zero_cnt_k(int n) {
    int i = blockIdx.x * blockDim.x + threadIdx.x;
    if (i < n) g_cnt[i] = 0;
}

__global__ void count_k(const int* __restrict__ dst, int E) {
    int i = blockIdx.x * blockDim.x + threadIdx.x;
    if (i < E) atomicAdd(&g_cnt[dst[i]], 1);
}

// hierarchical scan, stage 1: each block scans 1024 counts (4/thread)
__global__ void scan1_k(int n) {
    __shared__ int wsum[8];
    int tid = threadIdx.x, lane = tid & 31, warp = tid >> 5;
    int base = blockIdx.x * 1024 + tid * 4;
    int4 v = make_int4(0, 0, 0, 0);
    if (base + 3 < n) {
        v = *(const int4*)(g_cnt + base);
    } else {
        if (base + 0 < n) v.x = g_cnt[base + 0];
        if (base + 1 < n) v.y = g_cnt[base + 1];
        if (base + 2 < n) v.z = g_cnt[base + 2];
    }
    int s = v.x + v.y + v.z + v.w;
    int t = s;
    #pragma unroll
    for (int o = 1; o < 32; o <<= 1) {
        int u = __shfl_up_sync(0xffffffffu, t, o);
        if (lane >= o) t += u;
    }
    if (lane == 31) wsum[warp] = t;
    __syncthreads();
    if (warp == 0 && lane < 8) {
        int w = wsum[lane];
        #pragma unroll
        for (int o = 1; o < 8; o <<= 1) {
            int u = __shfl_up_sync(0xffu, w, o);
            if (lane >= o) w += u;
        }
        wsum[lane] = w;
    }
    __syncthreads();
    int excl = t - s + (warp ? wsum[warp - 1] : 0);
    int p0 = excl, p1 = p0 + v.x, p2 = p1 + v.y, p3 = p2 + v.z;
    if (base + 3 < n) {
        *(int4*)(g_rowptr + base) = make_int4(p0, p1, p2, p3);
    } else {
        if (base + 0 < n) g_rowptr[base + 0] = p0;
        if (base + 1 < n) g_rowptr[base + 1] = p1;
        if (base + 2 < n) g_rowptr[base + 2] = p2;
    }
    if (tid == 255) g_bsum[blockIdx.x] = excl + s;
}

// stage 2: scan up to 128 block sums
__global__ void scan2_k(int n, int nb) {
    __shared__ int wsum[4];
    int tid = threadIdx.x, lane = tid & 31, warp = tid >> 5;   // 128 threads
    int v = (tid < nb) ? g_bsum[tid] : 0;
    int t = v;
    #pragma unroll
    for (int o = 1; o < 32; o <<= 1) {
        int u = __shfl_up_sync(0xffffffffu, t, o);
        if (lane >= o) t += u;
    }
    if (lane == 31) wsum[warp] = t;
    __syncthreads();
    if (warp == 0 && lane < 4) {
        int w = wsum[lane];
        #pragma unroll
        for (int o = 1; o < 4; o <<= 1) {
            int u = __shfl_up_sync(0xfu, w, o);
            if (lane >= o) w += u;
        }
        wsum[lane] = w;
    }
    __syncthreads();
    int excl = t - v + (warp ? wsum[warp - 1] : 0);
    if (tid < nb) g_boff[tid] = excl;
    if (tid == 127) g_rowptr[n] = wsum[3];
}

// stage 3: add block offsets; fused dinv + cursor init
__global__ void scan3_k(int n) {
    int i = blockIdx.x * blockDim.x + threadIdx.x;
    if (i < n) {
        int rp = g_rowptr[i] + g_boff[i >> 10];
        g_rowptr[i] = rp;
        g_cursor[i] = rp;
        g_dinv[i] = rsqrtf((float)(g_cnt[i] + 1));   // +1 self-loop
    }
}

__global__ void fill_k(const int* __restrict__ src, const int* __restrict__ dst, int E) {
    int i = blockIdx.x * blockDim.x + threadIdx.x;
    if (i < E) {
        int p = atomicAdd(&g_cursor[dst[i]], 1);
        g_csr[p] = src[i];
    }
}

// ---------------- dense transform: g_h/g_hb = X @ W ----------------
// 256 threads; warp handles 4 rows; lane owns col pairs (2l,2l+1) and (64+2l,64+2l+1).
__global__ void gemm_k(const float* __restrict__ X, const float* __restrict__ W, int n) {
    extern __shared__ char smraw[];
    ull* sW = (ull*)smraw;          // [k][c2] : 128*64 ull = 64KB
    ull* sX = sW + D * 64;          // [r][k] splatted : 32*128 ull = 32KB
    int tid = threadIdx.x;

    const ull* W2 = (const ull*)W;  // row-major pairs contiguous
    for (int i = tid; i < D * 64; i += 256) sW[i] = W2[i];

    int row0 = blockIdx.x * 32;
    for (int i = tid; i < 32 * D; i += 256) {
        int r = i >> 7, k = i & 127;
        float v = (row0 + r < n) ? X[(size_t)(row0 + r) * D + k] : 0.f;
        sX[r * D + k] = pack2(v, v);
    }
    __syncthreads();

    int warp = tid >> 5, lane = tid & 31;
    const ull* xr = sX + (warp * 4) * D;
    ull acc[4][2] = {};

    #pragma unroll 4
    for (int k = 0; k < D; k++) {
        ull wa = sW[k * 64 + lane];
        ull wb = sW[k * 64 + 32 + lane];
        #pragma unroll
        for (int r = 0; r < 4; r++) {
            ull xv = xr[r * D + k];
            ffma2(acc[r][0], xv, wa);
            ffma2(acc[r][1], xv, wb);
        }
    }

    #pragma unroll
    for (int r = 0; r < 4; r++) {
        int row = row0 + warp * 4 + r;
        if (row < n) {
            float a, b, c, d;
            unpack2(acc[r][0], a, b);
            unpack2(acc[r][1], c, d);
            ull* hp = (ull*)(g_h + (size_t)row * D);
            hp[lane]      = acc[r][0];
            hp[32 + lane] = acc[r][1];
            uint* hb = g_hb + (size_t)row * 64;
            __nv_bfloat162 p0 = __floats2bfloat162_rn(a, b);   // cols (2l, 2l+1)
            __nv_bfloat162 p1 = __floats2bfloat162_rn(c, d);   // cols (64+2l, 64+2l+1)
            hb[lane]      = *(uint*)&p0;
            hb[32 + lane] = *(uint*)&p1;
        }
    }
}

// ---------------- aggregation: out = relu(agg + h), warp per node ----------------
// neighbor rows gathered from bf16 copy (256B/row); self + residual in fp32.
__global__ void agg_k(float4* __restrict__ out, int n) {
    int t = blockIdx.x * blockDim.x + threadIdx.x;
    int node = t >> 5;
    int lane = t & 31;
    if (node >= n) return;

    const float4* h4 = (const float4*)g_h;
    const uint2*  hb = (const uint2*)g_hb;   // uint2 at lane l = cols 4l..4l+3
    float dv = g_dinv[node];
    float4 hv = h4[(size_t)node * 32 + lane];
    float ws = dv * dv;                                  // self-loop norm
    float4 acc = make_float4(ws * hv.x, ws * hv.y, ws * hv.z, ws * hv.w);

    int s = g_rowptr[node], e = g_rowptr[node + 1];
    int i = s;
    for (; i + 3 < e; i += 4) {
        int u0 = g_csr[i], u1 = g_csr[i + 1], u2 = g_csr[i + 2], u3 = g_csr[i + 3];
        float w0 = g_dinv[u0] * dv, w1 = g_dinv[u1] * dv;
        float w2 = g_dinv[u2] * dv, w3 = g_dinv[u3] * dv;
        uint2 v0 = hb[(size_t)u0 * 32 + lane];
        uint2 v1 = hb[(size_t)u1 * 32 + lane];
        uint2 v2 = hb[(size_t)u2 * 32 + lane];
        uint2 v3 = hb[(size_t)u3 * 32 + lane];
        float a, b;
        bf2x(v0.x, a, b); acc.x += w0 * a; acc.y += w0 * b;
        bf2x(v0.y, a, b); acc.z += w0 * a; acc.w += w0 * b;
        bf2x(v1.x, a, b); acc.x += w1 * a; acc.y += w1 * b;
        bf2x(v1.y, a, b); acc.z += w1 * a; acc.w += w1 * b;
        bf2x(v2.x, a, b); acc.x += w2 * a; acc.y += w2 * b;
        bf2x(v2.y, a, b); acc.z += w2 * a; acc.w += w2 * b;
        bf2x(v3.x, a, b); acc.x += w3 * a; acc.y += w3 * b;
        bf2x(v3.y, a, b); acc.z += w3 * a; acc.w += w3 * b;
    }
    for (; i < e; i++) {
        int u = g_csr[i];
        float w = g_dinv[u] * dv;
        uint2 v = hb[(size_t)u * 32 + lane];
        float a, b;
        bf2x(v.x, a, b); acc.x += w * a; acc.y += w * b;
        bf2x(v.y, a, b); acc.z += w * a; acc.w += w * b;
    }

    out[(size_t)node * 32 + lane] = make_float4(
        fmaxf(acc.x + hv.x, 0.f), fmaxf(acc.y + hv.y, 0.f),
        fmaxf(acc.z + hv.z, 0.f), fmaxf(acc.w + hv.w, 0.f));
}

// ---------------- seed gather: warp per seed ----------------
__global__ void gather_k(const int* __restrict__ seeds, const float4* __restrict__ ent,
                         float4* __restrict__ out, int ns) {
    int t = blockIdx.x * blockDim.x + threadIdx.x;
    int s = t >> 5;
    int lane = t & 31;
    if (s < ns) out[(size_t)s * 32 + lane] = ent[(size_t)seeds[s] * 32 + lane];
}

// ---------------- launch ----------------
extern "C" void kernel_launch(void* const* d_in, const int* in_sizes, int n_in,
                              void* d_out, int out_size) {
    const int*   seeds_sr = (const int*)d_in[0];
    const int*   seeds_tg = (const int*)d_in[1];
    const int*   edges_sr = (const int*)d_in[2];
    const int*   edges_tg = (const int*)d_in[3];
    const float* emb_sr   = (const float*)d_in[4];
    const float* emb_tg   = (const float*)d_in[5];
    const float* W0       = (const float*)d_in[6];
    const float* W1       = (const float*)d_in[7];

    int S = in_sizes[0];
    int E = in_sizes[2] / 2;
    int N = in_sizes[4] / D;

    float* out     = (float*)d_out;
    float* sr_seed = out;
    float* tg_seed = sr_seed + (size_t)S * D;
    float* sr_ent  = tg_seed + (size_t)S * D;
    float* tg_ent  = sr_ent  + (size_t)N * D;

    void* xaddr = nullptr;
    cudaGetSymbolAddress(&xaddr, g_x);

    int smem = (D * 64 + 32 * D) * (int)sizeof(ull);   // 96 KB
    cudaFuncSetAttribute(gemm_k, cudaFuncAttributeMaxDynamicSharedMemorySize, smem);

    int nb = (N + 1023) / 1024;

    for (int g = 0; g < 2; g++) {
        const int*   edges = g ? edges_tg : edges_sr;
        const float* emb   = g ? emb_tg   : emb_sr;
        const int*   seeds = g ? seeds_tg : seeds_sr;
        float* ent      = g ? tg_ent  : sr_ent;
        float* seed_out = g ? tg_seed : sr_seed;
        const int* src = edges;
        const int* dst = edges + E;

        // CSR build; gemm for layer 1 interleaved early (no CSR dependency)
        // so the heavy gemm_k lands at profiled launch index 3.
        zero_cnt_k<<<(N + 255) / 256, 256>>>(N);
        count_k<<<(E + 255) / 256, 256>>>(dst, E);
        scan1_k<<<nb, 256>>>(N);
        gemm_k<<<(N + 31) / 32, 256, smem>>>(emb, W0, N);     // layer-1 dense
        scan2_k<<<1, 128>>>(N, nb);
        scan3_k<<<(N + 255) / 256, 256>>>(N);
        fill_k<<<(E + 255) / 256, 256>>>(src, dst, E);

        // layer 1 aggregation: x = relu(agg(h) + h)
        agg_k<<<((size_t)N * 32 + 255) / 256, 256>>>((float4*)xaddr, N);

        // layer 2
        gemm_k<<<(N + 31) / 32, 256, smem>>>((const float*)xaddr, W1, N);
        agg_k<<<((size_t)N * 32 + 255) / 256, 256>>>((float4*)ent, N);

        // seed gather
        gather_k<<<((size_t)S * 32 + 255) / 256, 256>>>(seeds, (const float4*)ent,
                                                        (float4*)seed_out, S);
    }
}

// round 9
// speedup vs baseline: 1.2521x; 1.1973x over previous
#include <cuda_runtime.h>
#include <cuda_bf16.h>

#define D 128
#define MAXN 100000
#define MAXE 1600000
#define XS 129   // padded ull row stride for X-splat (bank de-conflict)

typedef unsigned long long ull;
typedef unsigned int uint;

// ---------------- device scratch (no allocations allowed) ----------------
__device__ int   g_cnt[MAXN];
__device__ int   g_rowptr[MAXN + 1];
__device__ int   g_cursor[MAXN];
__device__ int   g_csr[MAXE];
__device__ float g_dinv[MAXN];
__device__ int   g_bsum[128];
__device__ int   g_boff[128];
__device__ float g_h[(size_t)MAXN * D];          // dense output, fp32 (self/residual)
__device__ uint  g_hb[(size_t)MAXN * (D / 2)];   // dense output, packed bf16x2 (gathers)
__device__ float g_x[(size_t)MAXN * D];          // layer-1 activation

// ---------------- packed f32x2 helpers ----------------
__device__ __forceinline__ ull pack2(float x, float y) {
    ull r;
    asm("mov.b64 %0, {%1, %2};" : "=l"(r) : "f"(x), "f"(y));
    return r;
}
__device__ __forceinline__ void unpack2(ull v, float& x, float& y) {
    asm("mov.b64 {%0, %1}, %2;" : "=f"(x), "=f"(y) : "l"(v));
}
__device__ __forceinline__ void ffma2(ull& acc, ull a, ull b) {
    asm("fma.rn.f32x2 %0, %1, %2, %0;" : "+l"(acc) : "l"(a), "l"(b));
}
__device__ __forceinline__ void bf2x(uint v, float& lo, float& hi) {
    lo = __uint_as_float(v << 16);
    hi = __uint_as_float(v & 0xffff0000u);
}
__device__ __forceinline__ void lds_v2u64(ull& a, ull& b, const void* p) {
    asm volatile("ld.shared.v2.u64 {%0, %1}, [%2];" : "=l"(a), "=l"(b) : "l"(__cvta_generic_to_shared(p)));
}

// ---------------- CSR build ----------------
__global__ void zero_cnt_k(int n) {
    int i = blockIdx.x * blockDim.x + threadIdx.x;
    if (i < n) g_cnt[i] = 0;
}

__global__ void count_k(const int* __restrict__ dst, int E) {
    int i = blockIdx.x * blockDim.x + threadIdx.x;
    if (i < E) atomicAdd(&g_cnt[dst[i]], 1);
}

__global__ void scan1_k(int n) {
    __shared__ int wsum[8];
    int tid = threadIdx.x, lane = tid & 31, warp = tid >> 5;
    int base = blockIdx.x * 1024 + tid * 4;
    int4 v = make_int4(0, 0, 0, 0);
    if (base + 3 < n) {
        v = *(const int4*)(g_cnt + base);
    } else {
        if (base + 0 < n) v.x = g_cnt[base + 0];
        if (base + 1 < n) v.y = g_cnt[base + 1];
        if (base + 2 < n) v.z = g_cnt[base + 2];
    }
    int s = v.x + v.y + v.z + v.w;
    int t = s;
    #pragma unroll
    for (int o = 1; o < 32; o <<= 1) {
        int u = __shfl_up_sync(0xffffffffu, t, o);
        if (lane >= o) t += u;
    }
    if (lane == 31) wsum[warp] = t;
    __syncthreads();
    if (warp == 0 && lane < 8) {
        int w = wsum[lane];
        #pragma unroll
        for (int o = 1; o < 8; o <<= 1) {
            int u = __shfl_up_sync(0xffu, w, o);
            if (lane >= o) w += u;
        }
        wsum[lane] = w;
    }
    __syncthreads();
    int excl = t - s + (warp ? wsum[warp - 1] : 0);
    int p0 = excl, p1 = p0 + v.x, p2 = p1 + v.y, p3 = p2 + v.z;
    if (base + 3 < n) {
        *(int4*)(g_rowptr + base) = make_int4(p0, p1, p2, p3);
    } else {
        if (base + 0 < n) g_rowptr[base + 0] = p0;
        if (base + 1 < n) g_rowptr[base + 1] = p1;
        if (base + 2 < n) g_rowptr[base + 2] = p2;
    }
    if (tid == 255) g_bsum[blockIdx.x] = excl + s;
}

__global__ void scan2_k(int n, int nb) {
    __shared__ int wsum[4];
    int tid = threadIdx.x, lane = tid & 31, warp = tid >> 5;
    int v = (tid < nb) ? g_bsum[tid] : 0;
    int t = v;
    #pragma unroll
    for (int o = 1; o < 32; o <<= 1) {
        int u = __shfl_up_sync(0xffffffffu, t, o);
        if (lane >= o) t += u;
    }
    if (lane == 31) wsum[warp] = t;
    __syncthreads();
    if (warp == 0 && lane < 4) {
        int w = wsum[lane];
        #pragma unroll
        for (int o = 1; o < 4; o <<= 1) {
            int u = __shfl_up_sync(0xfu, w, o);
            if (lane >= o) w += u;
        }
        wsum[lane] = w;
    }
    __syncthreads();
    int excl = t - v + (warp ? wsum[warp - 1] : 0);
    if (tid < nb) g_boff[tid] = excl;
    if (tid == 127) g_rowptr[n] = wsum[3];
}

__global__ void scan3_k(int n) {
    int i = blockIdx.x * blockDim.x + threadIdx.x;
    if (i < n) {
        int rp = g_rowptr[i] + g_boff[i >> 10];
        g_rowptr[i] = rp;
        g_cursor[i] = rp;
        g_dinv[i] = rsqrtf((float)(g_cnt[i] + 1));
    }
}

__global__ void fill_k(const int* __restrict__ src, const int* __restrict__ dst, int E) {
    int i = blockIdx.x * blockDim.x + threadIdx.x;
    if (i < E) {
        int p = atomicAdd(&g_cursor[dst[i]], 1);
        g_csr[p] = src[i];
    }
}

// ---------------- dense transform: g_h/g_hb = X @ W ----------------
// 128 rows/CTA, 256 threads as 16x16 grid. Thread (tx,ty):
//   rows ty*8..ty*8+7, cols {4tx..4tx+3} and {64+4tx..64+4tx+3} (8x8 tile).
// X pre-splatted in smem (broadcast LDS.64), W as conflict-free LDS.128 pairs.
__global__ __launch_bounds__(256, 1) void gemm8_k(const float* __restrict__ X,
                                                  const float* __restrict__ W, int n) {
    extern __shared__ char sm[];
    float4* sW4 = (float4*)sm;               // [k*32 + c4] : 64KB
    ull*    sXs = (ull*)(sm + 65536);        // [r*XS + k] splatted : 128*129*8 = 132KB
    int tid = threadIdx.x;
    int row0 = blockIdx.x * 128;

    const float4* W4 = (const float4*)W;
    for (int i = tid; i < D * 32; i += 256) sW4[i] = W4[i];

    for (int i = tid; i < 128 * D; i += 256) {
        int r = i >> 7, k = i & 127;
        int row = row0 + r;
        float v = (row < n) ? X[(size_t)row * D + k] : 0.f;
        sXs[r * XS + k] = pack2(v, v);
    }
    __syncthreads();

    int lane = tid & 31, wid = tid >> 5;
    int tx = lane & 15;
    int ty = wid * 2 + (lane >> 4);
    const ull* xb = sXs + (ty * 8) * XS;

    ull acc[8][4] = {};   // [row i][pair]: 0,1 -> cols 4tx..; 2,3 -> cols 64+4tx..

    #pragma unroll 4
    for (int k = 0; k < D; k++) {
        ull w0a, w0b, w1a, w1b;
        lds_v2u64(w0a, w0b, sW4 + k * 32 + tx);        // cols 4tx..4tx+3
        lds_v2u64(w1a, w1b, sW4 + k * 32 + 16 + tx);   // cols 64+4tx..+3
        #pragma unroll
        for (int i = 0; i < 8; i++) {
            ull xv = xb[i * XS + k];
            ffma2(acc[i][0], xv, w0a);
            ffma2(acc[i][1], xv, w0b);
            ffma2(acc[i][2], xv, w1a);
            ffma2(acc[i][3], xv, w1b);
        }
    }

    #pragma unroll
    for (int i = 0; i < 8; i++) {
        int row = row0 + ty * 8 + i;
        if (row < n) {
            ull* hp = (ull*)(g_h + (size_t)row * D);
            hp[2 * tx]      = acc[i][0];
            hp[2 * tx + 1]  = acc[i][1];
            hp[32 + 2 * tx]     = acc[i][2];
            hp[32 + 2 * tx + 1] = acc[i][3];
            float a, b, c, d2;
            uint2* hb = (uint2*)(g_hb + (size_t)row * 64);
            unpack2(acc[i][0], a, b);
            unpack2(acc[i][1], c, d2);
            __nv_bfloat162 p0 = __floats2bfloat162_rn(a, b);
            __nv_bfloat162 p1 = __floats2bfloat162_rn(c, d2);
            hb[tx] = make_uint2(*(uint*)&p0, *(uint*)&p1);
            unpack2(acc[i][2], a, b);
            unpack2(acc[i][3], c, d2);
            __nv_bfloat162 p2 = __floats2bfloat162_rn(a, b);
            __nv_bfloat162 p3 = __floats2bfloat162_rn(c, d2);
            hb[16 + tx] = make_uint2(*(uint*)&p2, *(uint*)&p3);
        }
    }
}

// ---------------- aggregation: out = relu(agg + h), warp per node ----------------
__global__ void agg_k(float4* __restrict__ out, int n) {
    int t = blockIdx.x * blockDim.x + threadIdx.x;
    int node = t >> 5;
    int lane = t & 31;
    if (node >= n) return;

    const float4* h4 = (const float4*)g_h;
    const uint2*  hb = (const uint2*)g_hb;
    float dv = g_dinv[node];
    float4 hv = h4[(size_t)node * 32 + lane];
    float ws = dv * dv;
    float4 acc = make_float4(ws * hv.x, ws * hv.y, ws * hv.z, ws * hv.w);

    int s = g_rowptr[node], e = g_rowptr[node + 1];
    int i = s;
    for (; i + 3 < e; i += 4) {
        int u0 = g_csr[i], u1 = g_csr[i + 1], u2 = g_csr[i + 2], u3 = g_csr[i + 3];
        float w0 = g_dinv[u0] * dv, w1 = g_dinv[u1] * dv;
        float w2 = g_dinv[u2] * dv, w3 = g_dinv[u3] * dv;
        uint2 v0 = hb[(size_t)u0 * 32 + lane];
        uint2 v1 = hb[(size_t)u1 * 32 + lane];
        uint2 v2 = hb[(size_t)u2 * 32 + lane];
        uint2 v3 = hb[(size_t)u3 * 32 + lane];
        float a, b;
        bf2x(v0.x, a, b); acc.x += w0 * a; acc.y += w0 * b;
        bf2x(v0.y, a, b); acc.z += w0 * a; acc.w += w0 * b;
        bf2x(v1.x, a, b); acc.x += w1 * a; acc.y += w1 * b;
        bf2x(v1.y, a, b); acc.z += w1 * a; acc.w += w1 * b;
        bf2x(v2.x, a, b); acc.x += w2 * a; acc.y += w2 * b;
        bf2x(v2.y, a, b); acc.z += w2 * a; acc.w += w2 * b;
        bf2x(v3.x, a, b); acc.x += w3 * a; acc.y += w3 * b;
        bf2x(v3.y, a, b); acc.z += w3 * a; acc.w += w3 * b;
    }
    for (; i < e; i++) {
        int u = g_csr[i];
        float w = g_dinv[u] * dv;
        uint2 v = hb[(size_t)u * 32 + lane];
        float a, b;
        bf2x(v.x, a, b); acc.x += w * a; acc.y += w * b;
        bf2x(v.y, a, b); acc.z += w * a; acc.w += w * b;
    }

    out[(size_t)node * 32 + lane] = make_float4(
        fmaxf(acc.x + hv.x, 0.f), fmaxf(acc.y + hv.y, 0.f),
        fmaxf(acc.z + hv.z, 0.f), fmaxf(acc.w + hv.w, 0.f));
}

// ---------------- seed gather: warp per seed ----------------
__global__ void gather_k(const int* __restrict__ seeds, const float4* __restrict__ ent,
                         float4* __restrict__ out, int ns) {
    int t = blockIdx.x * blockDim.x + threadIdx.x;
    int s = t >> 5;
    int lane = t & 31;
    if (s < ns) out[(size_t)s * 32 + lane] = ent[(size_t)seeds[s] * 32 + lane];
}

// ---------------- launch ----------------
extern "C" void kernel_launch(void* const* d_in, const int* in_sizes, int n_in,
                              void* d_out, int out_size) {
    const int*   seeds_sr = (const int*)d_in[0];
    const int*   seeds_tg = (const int*)d_in[1];
    const int*   edges_sr = (const int*)d_in[2];
    const int*   edges_tg = (const int*)d_in[3];
    const float* emb_sr   = (const float*)d_in[4];
    const float* emb_tg   = (const float*)d_in[5];
    const float* W0       = (const float*)d_in[6];
    const float* W1       = (const float*)d_in[7];

    int S = in_sizes[0];
    int E = in_sizes[2] / 2;
    int N = in_sizes[4] / D;

    float* out     = (float*)d_out;
    float* sr_seed = out;
    float* tg_seed = sr_seed + (size_t)S * D;
    float* sr_ent  = tg_seed + (size_t)S * D;
    float* tg_ent  = sr_ent  + (size_t)N * D;

    void* xaddr = nullptr;
    cudaGetSymbolAddress(&xaddr, g_x);

    int smem = 65536 + 128 * XS * 8;   // 64KB W + 132KB X-splat = 196.6KB
    cudaFuncSetAttribute(gemm8_k, cudaFuncAttributeMaxDynamicSharedMemorySize, smem);

    int nb = (N + 1023) / 1024;
    int gtiles = (N + 127) / 128;

    for (int g = 0; g < 2; g++) {
        const int*   edges = g ? edges_tg : edges_sr;
        const float* emb   = g ? emb_tg   : emb_sr;
        const int*   seeds = g ? seeds_tg : seeds_sr;
        float* ent      = g ? tg_ent  : sr_ent;
        float* seed_out = g ? tg_seed : sr_seed;
        const int* src = edges;
        const int* dst = edges + E;

        zero_cnt_k<<<(N + 255) / 256, 256>>>(N);
        count_k<<<(E + 255) / 256, 256>>>(dst, E);
        scan1_k<<<nb, 256>>>(N);
        gemm8_k<<<gtiles, 256, smem>>>(emb, W0, N);   // layer-1 dense (profiled idx 3)
        scan2_k<<<1, 128>>>(N, nb);
        scan3_k<<<(N + 255) / 256, 256>>>(N);
        fill_k<<<(E + 255) / 256, 256>>>(src, dst, E);

        agg_k<<<((size_t)N * 32 + 255) / 256, 256>>>((float4*)xaddr, N);

        gemm8_k<<<gtiles, 256, smem>>>((const float*)xaddr, W1, N);
        agg_k<<<((size_t)N * 32 + 255) / 256, 256>>>((float4*)ent, N);

        gather_k<<<((size_t)S * 32 + 255) / 256, 256>>>(seeds, (const float4*)ent,
                                                        (float4*)seed_out, S);
    }
}

// round 10
// speedup vs baseline: 1.4144x; 1.1296x over previous
#include <cuda_runtime.h>
#include <cuda_bf16.h>

#define D 128
#define MAXN 100000
#define MAXE 1600000
#define XS 129   // padded ull row stride for X-splat (bank de-conflict)

typedef unsigned long long ull;
typedef unsigned int uint;

// ---------------- device scratch (no allocations allowed) ----------------
__device__ int   g_cnt[MAXN];
__device__ int   g_rowptr[MAXN + 1];
__device__ int   g_cursor[MAXN];
__device__ int   g_csr[MAXE];
__device__ float g_dinv[MAXN];
__device__ int   g_bsum[128];
__device__ int   g_boff[128];
__device__ float g_h[(size_t)MAXN * D];          // dense output, fp32 (self/residual)
__device__ uint  g_hb[(size_t)MAXN * (D / 2)];   // dense output, packed bf16x2 (gathers)
__device__ float g_x[(size_t)MAXN * D];          // layer-1 activation

// ---------------- packed f32x2 helpers ----------------
__device__ __forceinline__ ull pack2(float x, float y) {
    ull r;
    asm("mov.b64 %0, {%1, %2};" : "=l"(r) : "f"(x), "f"(y));
    return r;
}
__device__ __forceinline__ void unpack2(ull v, float& x, float& y) {
    asm("mov.b64 {%0, %1}, %2;" : "=f"(x), "=f"(y) : "l"(v));
}
__device__ __forceinline__ void ffma2(ull& acc, ull a, ull b) {
    asm("fma.rn.f32x2 %0, %1, %2, %0;" : "+l"(acc) : "l"(a), "l"(b));
}
__device__ __forceinline__ void bf2x(uint v, float& lo, float& hi) {
    lo = __uint_as_float(v << 16);
    hi = __uint_as_float(v & 0xffff0000u);
}
__device__ __forceinline__ void lds_v2u64(ull& a, ull& b, const void* p) {
    asm volatile("ld.shared.v2.u64 {%0, %1}, [%2];" : "=l"(a), "=l"(b) : "l"(__cvta_generic_to_shared(p)));
}

// ---------------- CSR build ----------------
__global__ void zero_cnt_k(int n) {
    int i = blockIdx.x * blockDim.x + threadIdx.x;
    if (i < n) g_cnt[i] = 0;
}

__global__ void count_k(const int* __restrict__ dst, int E) {
    int i = blockIdx.x * blockDim.x + threadIdx.x;
    if (i < E) atomicAdd(&g_cnt[dst[i]], 1);
}

__global__ void scan1_k(int n) {
    __shared__ int wsum[8];
    int tid = threadIdx.x, lane = tid & 31, warp = tid >> 5;
    int base = blockIdx.x * 1024 + tid * 4;
    int4 v = make_int4(0, 0, 0, 0);
    if (base + 3 < n) {
        v = *(const int4*)(g_cnt + base);
    } else {
        if (base + 0 < n) v.x = g_cnt[base + 0];
        if (base + 1 < n) v.y = g_cnt[base + 1];
        if (base + 2 < n) v.z = g_cnt[base + 2];
    }
    int s = v.x + v.y + v.z + v.w;
    int t = s;
    #pragma unroll
    for (int o = 1; o < 32; o <<= 1) {
        int u = __shfl_up_sync(0xffffffffu, t, o);
        if (lane >= o) t += u;
    }
    if (lane == 31) wsum[warp] = t;
    __syncthreads();
    if (warp == 0 && lane < 8) {
        int w = wsum[lane];
        #pragma unroll
        for (int o = 1; o < 8; o <<= 1) {
            int u = __shfl_up_sync(0xffu, w, o);
            if (lane >= o) w += u;
        }
        wsum[lane] = w;
    }
    __syncthreads();
    int excl = t - s + (warp ? wsum[warp - 1] : 0);
    int p0 = excl, p1 = p0 + v.x, p2 = p1 + v.y, p3 = p2 + v.z;
    if (base + 3 < n) {
        *(int4*)(g_rowptr + base) = make_int4(p0, p1, p2, p3);
    } else {
        if (base + 0 < n) g_rowptr[base + 0] = p0;
        if (base + 1 < n) g_rowptr[base + 1] = p1;
        if (base + 2 < n) g_rowptr[base + 2] = p2;
    }
    if (tid == 255) g_bsum[blockIdx.x] = excl + s;
}

__global__ void scan2_k(int n, int nb) {
    __shared__ int wsum[4];
    int tid = threadIdx.x, lane = tid & 31, warp = tid >> 5;
    int v = (tid < nb) ? g_bsum[tid] : 0;
    int t = v;
    #pragma unroll
    for (int o = 1; o < 32; o <<= 1) {
        int u = __shfl_up_sync(0xffffffffu, t, o);
        if (lane >= o) t += u;
    }
    if (lane == 31) wsum[warp] = t;
    __syncthreads();
    if (warp == 0 && lane < 4) {
        int w = wsum[lane];
        #pragma unroll
        for (int o = 1; o < 4; o <<= 1) {
            int u = __shfl_up_sync(0xfu, w, o);
            if (lane >= o) w += u;
        }
        wsum[lane] = w;
    }
    __syncthreads();
    int excl = t - v + (warp ? wsum[warp - 1] : 0);
    if (tid < nb) g_boff[tid] = excl;
    if (tid == 127) g_rowptr[n] = wsum[3];
}

__global__ void scan3_k(int n) {
    int i = blockIdx.x * blockDim.x + threadIdx.x;
    if (i < n) {
        int rp = g_rowptr[i] + g_boff[i >> 10];
        g_rowptr[i] = rp;
        g_cursor[i] = rp;
        g_dinv[i] = rsqrtf((float)(g_cnt[i] + 1));
    }
}

__global__ void fill_k(const int* __restrict__ src, const int* __restrict__ dst, int E) {
    int i = blockIdx.x * blockDim.x + threadIdx.x;
    if (i < E) {
        int p = atomicAdd(&g_cursor[dst[i]], 1);
        g_csr[p] = src[i];
    }
}

// ---------------- dense transform: g_h/g_hb = X @ W ----------------
// 128 rows/CTA, 512 threads as 16(tx) x 32(ty) grid. Thread (tx,ty):
//   rows ty*4..ty*4+3, cols {4tx..4tx+3} and {64+4tx..64+4tx+3} (4x8 tile).
// 16 warps/SM = 4/SMSP for latency hiding; acc = 16 ull = 32 regs.
__global__ __launch_bounds__(512, 1) void gemm8_k(const float* __restrict__ X,
                                                  const float* __restrict__ W, int n) {
    extern __shared__ char sm[];
    float4* sW4 = (float4*)sm;               // [k*32 + c4] : 64KB
    ull*    sXs = (ull*)(sm + 65536);        // [r*XS + k] splatted : 132KB
    int tid = threadIdx.x;
    int row0 = blockIdx.x * 128;

    const float4* W4 = (const float4*)W;
    for (int i = tid; i < D * 32; i += 512) sW4[i] = W4[i];

    for (int i = tid; i < 128 * D; i += 512) {
        int r = i >> 7, k = i & 127;
        int row = row0 + r;
        float v = (row < n) ? X[(size_t)row * D + k] : 0.f;
        sXs[r * XS + k] = pack2(v, v);
    }
    __syncthreads();

    int lane = tid & 31, wid = tid >> 5;
    int tx = lane & 15;
    int ty = wid * 2 + (lane >> 4);          // 0..31
    const ull* xb = sXs + (ty * 4) * XS;

    ull acc[4][4] = {};   // [row i][pair]: 0,1 -> cols 4tx..; 2,3 -> cols 64+4tx..

    #pragma unroll 4
    for (int k = 0; k < D; k++) {
        ull w0a, w0b, w1a, w1b;
        lds_v2u64(w0a, w0b, sW4 + k * 32 + tx);        // cols 4tx..4tx+3
        lds_v2u64(w1a, w1b, sW4 + k * 32 + 16 + tx);   // cols 64+4tx..+3
        #pragma unroll
        for (int i = 0; i < 4; i++) {
            ull xv = xb[i * XS + k];
            ffma2(acc[i][0], xv, w0a);
            ffma2(acc[i][1], xv, w0b);
            ffma2(acc[i][2], xv, w1a);
            ffma2(acc[i][3], xv, w1b);
        }
    }

    #pragma unroll
    for (int i = 0; i < 4; i++) {
        int row = row0 + ty * 4 + i;
        if (row < n) {
            ull* hp = (ull*)(g_h + (size_t)row * D);
            hp[2 * tx]          = acc[i][0];
            hp[2 * tx + 1]      = acc[i][1];
            hp[32 + 2 * tx]     = acc[i][2];
            hp[32 + 2 * tx + 1] = acc[i][3];
            float a, b, c, d2;
            uint2* hb = (uint2*)(g_hb + (size_t)row * 64);
            unpack2(acc[i][0], a, b);
            unpack2(acc[i][1], c, d2);
            __nv_bfloat162 p0 = __floats2bfloat162_rn(a, b);
            __nv_bfloat162 p1 = __floats2bfloat162_rn(c, d2);
            hb[tx] = make_uint2(*(uint*)&p0, *(uint*)&p1);
            unpack2(acc[i][2], a, b);
            unpack2(acc[i][3], c, d2);
            __nv_bfloat162 p2 = __floats2bfloat162_rn(a, b);
            __nv_bfloat162 p3 = __floats2bfloat162_rn(c, d2);
            hb[16 + tx] = make_uint2(*(uint*)&p2, *(uint*)&p3);
        }
    }
}

// ---------------- aggregation: out = relu(agg + h), warp per node ----------------
__global__ void agg_k(float4* __restrict__ out, int n) {
    int t = blockIdx.x * blockDim.x + threadIdx.x;
    int node = t >> 5;
    int lane = t & 31;
    if (node >= n) return;

    const float4* h4 = (const float4*)g_h;
    const uint2*  hb = (const uint2*)g_hb;
    float dv = g_dinv[node];
    float4 hv = h4[(size_t)node * 32 + lane];
    float ws = dv * dv;
    float4 acc = make_float4(ws * hv.x, ws * hv.y, ws * hv.z, ws * hv.w);

    int s = g_rowptr[node], e = g_rowptr[node + 1];
    int i = s;
    for (; i + 3 < e; i += 4) {
        int u0 = g_csr[i], u1 = g_csr[i + 1], u2 = g_csr[i + 2], u3 = g_csr[i + 3];
        float w0 = g_dinv[u0] * dv, w1 = g_dinv[u1] * dv;
        float w2 = g_dinv[u2] * dv, w3 = g_dinv[u3] * dv;
        uint2 v0 = hb[(size_t)u0 * 32 + lane];
        uint2 v1 = hb[(size_t)u1 * 32 + lane];
        uint2 v2 = hb[(size_t)u2 * 32 + lane];
        uint2 v3 = hb[(size_t)u3 * 32 + lane];
        float a, b;
        bf2x(v0.x, a, b); acc.x += w0 * a; acc.y += w0 * b;
        bf2x(v0.y, a, b); acc.z += w0 * a; acc.w += w0 * b;
        bf2x(v1.x, a, b); acc.x += w1 * a; acc.y += w1 * b;
        bf2x(v1.y, a, b); acc.z += w1 * a; acc.w += w1 * b;
        bf2x(v2.x, a, b); acc.x += w2 * a; acc.y += w2 * b;
        bf2x(v2.y, a, b); acc.z += w2 * a; acc.w += w2 * b;
        bf2x(v3.x, a, b); acc.x += w3 * a; acc.y += w3 * b;
        bf2x(v3.y, a, b); acc.z += w3 * a; acc.w += w3 * b;
    }
    for (; i < e; i++) {
        int u = g_csr[i];
        float w = g_dinv[u] * dv;
        uint2 v = hb[(size_t)u * 32 + lane];
        float a, b;
        bf2x(v.x, a, b); acc.x += w * a; acc.y += w * b;
        bf2x(v.y, a, b); acc.z += w * a; acc.w += w * b;
    }

    out[(size_t)node * 32 + lane] = make_float4(
        fmaxf(acc.x + hv.x, 0.f), fmaxf(acc.y + hv.y, 0.f),
        fmaxf(acc.z + hv.z, 0.f), fmaxf(acc.w + hv.w, 0.f));
}

// ---------------- seed gather: warp per seed ----------------
__global__ void gather_k(const int* __restrict__ seeds, const float4* __restrict__ ent,
                         float4* __restrict__ out, int ns) {
    int t = blockIdx.x * blockDim.x + threadIdx.x;
    int s = t >> 5;
    int lane = t & 31;
    if (s < ns) out[(size_t)s * 32 + lane] = ent[(size_t)seeds[s] * 32 + lane];
}

// ---------------- launch ----------------
extern "C" void kernel_launch(void* const* d_in, const int* in_sizes, int n_in,
                              void* d_out, int out_size) {
    const int*   seeds_sr = (const int*)d_in[0];
    const int*   seeds_tg = (const int*)d_in[1];
    const int*   edges_sr = (const int*)d_in[2];
    const int*   edges_tg = (const int*)d_in[3];
    const float* emb_sr   = (const float*)d_in[4];
    const float* emb_tg   = (const float*)d_in[5];
    const float* W0       = (const float*)d_in[6];
    const float* W1       = (const float*)d_in[7];

    int S = in_sizes[0];
    int E = in_sizes[2] / 2;
    int N = in_sizes[4] / D;

    float* out     = (float*)d_out;
    float* sr_seed = out;
    float* tg_seed = sr_seed + (size_t)S * D;
    float* sr_ent  = tg_seed + (size_t)S * D;
    float* tg_ent  = sr_ent  + (size_t)N * D;

    void* xaddr = nullptr;
    cudaGetSymbolAddress(&xaddr, g_x);

    int smem = 65536 + 128 * XS * 8;   // 64KB W + 132KB X-splat = 196.6KB
    cudaFuncSetAttribute(gemm8_k, cudaFuncAttributeMaxDynamicSharedMemorySize, smem);

    int nb = (N + 1023) / 1024;
    int gtiles = (N + 127) / 128;

    for (int g = 0; g < 2; g++) {
        const int*   edges = g ? edges_tg : edges_sr;
        const float* emb   = g ? emb_tg   : emb_sr;
        const int*   seeds = g ? seeds_tg : seeds_sr;
        float* ent      = g ? tg_ent  : sr_ent;
        float* seed_out = g ? tg_seed : sr_seed;
        const int* src = edges;
        const int* dst = edges + E;

        zero_cnt_k<<<(N + 255) / 256, 256>>>(N);
        count_k<<<(E + 255) / 256, 256>>>(dst, E);
        scan1_k<<<nb, 256>>>(N);
        gemm8_k<<<gtiles, 512, smem>>>(emb, W0, N);   // layer-1 dense (profiled idx 3)
        scan2_k<<<1, 128>>>(N, nb);
        scan3_k<<<(N + 255) / 256, 256>>>(N);
        fill_k<<<(E + 255) / 256, 256>>>(src, dst, E);

        agg_k<<<((size_t)N * 32 + 255) / 256, 256>>>((float4*)xaddr, N);

        gemm8_k<<<gtiles, 512, smem>>>((const float*)xaddr, W1, N);
        agg_k<<<((size_t)N * 32 + 255) / 256, 256>>>((float4*)ent, N);

        gather_k<<<((size_t)S * 32 + 255) / 256, 256>>>(seeds, (const float4*)ent,
                                                        (float4*)seed_out, S);
    }
}